// round 12
// baseline (speedup 1.0000x reference)
#include <cuda_runtime.h>

#define BB 8
#define NN 4096
#define DD 64
#define SS 1024
#define KK 32
#define CDIM 131   // 64 + 3 + 64

__device__ int g_fps_idx[BB * SS];

// ---------------------------------------------------------------------------
// FPS: one block per batch, 512 threads, 8 points per thread (coords + running
// min-distance kept entirely in registers). Exact no-FMA arithmetic to match
// jnp.sum((xyz - centroid)**2, -1) with accumulation order (dx2+dy2)+dz2.
// argmax tie-break = first (lowest) index, matching jnp.argmax.
// (Verified bit-exact in R2: output 0 passed with rel_err = 0.)
// ---------------------------------------------------------------------------
__global__ __launch_bounds__(512, 1) void fps_kernel(const float* __restrict__ xyz)
{
    const int b    = blockIdx.x;
    const int tid  = threadIdx.x;
    const int lane = tid & 31;
    const int w    = tid >> 5;
    const float* bx = xyz + (size_t)b * NN * 3;

    float px[8], py[8], pz[8], dist[8];
#pragma unroll
    for (int j = 0; j < 8; ++j) {
        int i = tid + j * 512;
        px[j] = bx[i * 3 + 0];
        py[j] = bx[i * 3 + 1];
        pz[j] = bx[i * 3 + 2];
        dist[j] = 10000000000.0f;
    }

    __shared__ float s_val[16];
    __shared__ int   s_idx[16];
    __shared__ int   s_far;

    int far = 0;
    for (int it = 0; it < SS; ++it) {
        if (tid == 0) g_fps_idx[b * SS + it] = far;

        const float cx = __ldg(bx + far * 3 + 0);
        const float cy = __ldg(bx + far * 3 + 1);
        const float cz = __ldg(bx + far * 3 + 2);

        float bv = -1.0f;
        int   bi = 0;
#pragma unroll
        for (int j = 0; j < 8; ++j) {
            float dx = __fadd_rn(px[j], -cx);
            float dy = __fadd_rn(py[j], -cy);
            float dz = __fadd_rn(pz[j], -cz);
            float dd = __fadd_rn(__fadd_rn(__fmul_rn(dx, dx), __fmul_rn(dy, dy)),
                                 __fmul_rn(dz, dz));
            float nd = fminf(dist[j], dd);
            dist[j] = nd;
            // indices ascend with j, so strict > keeps first occurrence
            if (nd > bv) { bv = nd; bi = tid + j * 512; }
        }

        // warp reduction (val, idx), ties -> lower idx
#pragma unroll
        for (int o = 16; o > 0; o >>= 1) {
            float ov = __shfl_down_sync(0xffffffffu, bv, o);
            int   oi = __shfl_down_sync(0xffffffffu, bi, o);
            if (ov > bv || (ov == bv && oi < bi)) { bv = ov; bi = oi; }
        }
        if (lane == 0) { s_val[w] = bv; s_idx[w] = bi; }
        __syncthreads();

        if (w == 0) {
            float v2 = (lane < 16) ? s_val[lane] : -1.0f;
            int   i2 = (lane < 16) ? s_idx[lane] : 0;
#pragma unroll
            for (int o = 8; o > 0; o >>= 1) {
                float ov = __shfl_down_sync(0xffffffffu, v2, o);
                int   oi = __shfl_down_sync(0xffffffffu, i2, o);
                if (ov > v2 || (ov == v2 && oi < i2)) { v2 = ov; i2 = oi; }
            }
            if (lane == 0) s_far = i2;
        }
        __syncthreads();
        far = s_far;
    }
}

// ---------------------------------------------------------------------------
// Fused ball-query + gather. Distance replicates the reference's lowering:
//   dot  = fma(qz,z, fma(qy,y, qx*x))        (GEMM-style FMA accumulation, k asc)
//   nrm  = (x*x + y*y) + z*z                 (square materialized, plain adds)
//   d    = ((-2*dot) + srcn) + dstn          (broadcast-add fusion order)
// ---------------------------------------------------------------------------
__global__ __launch_bounds__(128) void group_kernel(const float* __restrict__ xyz,
                                                    const float* __restrict__ pts,
                                                    float* __restrict__ out_xyz,
                                                    float* __restrict__ out_pts)
{
    const int bs   = blockIdx.x;        // b*S + s
    const int b    = bs >> 10;
    const int tid  = threadIdx.x;
    const int lane = tid & 31;
    const int w    = tid >> 5;

    const float* bx = xyz + (size_t)b * NN * 3;
    const float* pb = pts + (size_t)b * NN * DD;

    const int a = g_fps_idx[bs];
    const float qx = __ldg(bx + a * 3 + 0);
    const float qy = __ldg(bx + a * 3 + 1);
    const float qz = __ldg(bx + a * 3 + 2);
    const float srcn = __fadd_rn(__fadd_rn(__fmul_rn(qx, qx), __fmul_rn(qy, qy)),
                                 __fmul_rn(qz, qz));
    const float r2 = 0.04f;

    __shared__ int seg_buf[4][KK];
    __shared__ int counts[4];
    __shared__ int gidx[KK];

    // ---- ball query: each warp scans its 1024-point segment in index order
    {
        int cnt = 0;
        const int segbase = w * 1024;
        for (int c = 0; c < 32; ++c) {
            int p = segbase + c * 32 + lane;
            float x = __ldg(bx + p * 3 + 0);
            float y = __ldg(bx + p * 3 + 1);
            float z = __ldg(bx + p * 3 + 2);
            // GEMM-style FMA dot, ascending component order
            float dot = __fmaf_rn(qz, z, __fmaf_rn(qy, y, __fmul_rn(qx, x)));
            float dn  = __fadd_rn(__fadd_rn(__fmul_rn(x, x), __fmul_rn(y, y)),
                                  __fmul_rn(z, z));
            float d   = __fadd_rn(__fadd_rn(__fmul_rn(-2.0f, dot), srcn), dn);
            bool hit = !(d > r2);
            unsigned m = __ballot_sync(0xffffffffu, hit);
            if (hit) {
                int r = cnt + __popc(m & ((1u << lane) - 1u));
                if (r < KK) seg_buf[w][r] = p;
            }
            cnt += __popc(m);
            if (cnt >= KK) break;
        }
        if (lane == 0) counts[w] = cnt < KK ? cnt : KK;
    }
    __syncthreads();

    // ---- merge first-32 across segments (threads 0..31)
    if (tid < KK) {
        int c0 = counts[0], c1 = counts[1], c2 = counts[2], c3 = counts[3];
        int o1 = c0, o2 = c0 + c1, o3 = o2 + c2, tot = o3 + c3;
        int w0 = (c0 > 0) ? 0 : ((c1 > 0) ? 1 : ((c2 > 0) ? 2 : 3));
        int g0 = seg_buf[w0][0];
        int j = tid;
        int g;
        if (j < tot) {
            int ws, off;
            if      (j < o1) { ws = 0; off = j; }
            else if (j < o2) { ws = 1; off = j - o1; }
            else if (j < o3) { ws = 2; off = j - o2; }
            else             { ws = 3; off = j - o3; }
            g = seg_buf[ws][off];
        } else {
            g = g0;  // fill with first in-radius index (anchor guarantees >=1 hit)
        }
        gidx[j] = g;
    }
    // new_xyz
    if (tid < 3) out_xyz[(size_t)bs * 3 + tid] = __ldg(bx + a * 3 + tid);
    __syncthreads();

    // ---- gather + concat writes: row = [points[g] (64) | xyz[g] (3) | points[a] (64)]
    float av  = 0.0f, av2 = 0.0f;
    if (tid >= 67) av  = __ldg(pb + (size_t)a * DD + (tid - 67));
    if (tid < 3)   av2 = __ldg(pb + (size_t)a * DD + 61 + tid);   // elems 128..130 -> anchor[61..63]

    float* base0 = out_pts + (size_t)bs * KK * CDIM;
#pragma unroll 4
    for (int k = 0; k < KK; ++k) {
        int g = gidx[k];
        float v;
        if (tid < 64)      v = __ldg(pb + (size_t)g * DD + tid);
        else if (tid < 67) v = __ldg(bx + (size_t)g * 3 + (tid - 64));
        else               v = av;
        float* row = base0 + (size_t)k * CDIM;
        row[tid] = v;
        if (tid < 3) row[128 + tid] = av2;
    }
}

extern "C" void kernel_launch(void* const* d_in, const int* in_sizes, int n_in,
                              void* d_out, int out_size)
{
    const float* xyz = (const float*)d_in[0];   // [B, N, 3]
    const float* pts = (const float*)d_in[1];   // [B, N, D]
    float* out = (float*)d_out;
    float* out_xyz = out;                       // [B, S, 3]
    float* out_pts = out + (size_t)BB * SS * 3; // [B, S, K, 131]

    fps_kernel<<<BB, 512>>>(xyz);
    group_kernel<<<BB * SS, 128>>>(xyz, pts, out_xyz, out_pts);
}

// round 13
// speedup vs baseline: 1.4834x; 1.4834x over previous
#include <cuda_runtime.h>

#define BB 8
#define NN 4096
#define DD 64
#define SS 1024
#define KK 32
#define CDIM 131   // 64 + 3 + 64

__device__ int g_fps_idx[BB * SS];

// ---- packed f32x2 helpers (per-lane IEEE identical to scalar FADD/FMUL) ----
__device__ __forceinline__ unsigned long long f2_pack(float lo, float hi) {
    unsigned long long r;
    asm("mov.b64 %0, {%1, %2};" : "=l"(r) : "f"(lo), "f"(hi));
    return r;
}
__device__ __forceinline__ void f2_unpack(float& lo, float& hi, unsigned long long v) {
    asm("mov.b64 {%0, %1}, %2;" : "=f"(lo), "=f"(hi) : "l"(v));
}
__device__ __forceinline__ unsigned long long f2_add(unsigned long long a, unsigned long long b) {
    unsigned long long r;
    asm("add.rn.f32x2 %0, %1, %2;" : "=l"(r) : "l"(a), "l"(b));
    return r;
}
__device__ __forceinline__ unsigned long long f2_mul(unsigned long long a, unsigned long long b) {
    unsigned long long r;
    asm("mul.rn.f32x2 %0, %1, %2;" : "=l"(r) : "l"(a), "l"(b));
    return r;
}

// ---------------------------------------------------------------------------
// FPS: one block per batch, 512 threads, 8 points per thread held in packed
// f32x2 register pairs. Arithmetic is bit-identical to the verified-exact R2
// form: dx = px + (-cx); dd = (dx*dx + dy*dy) + dz*dz; nd = fminf(dist, dd).
// Argmax: depth-3 select tree (>= prefers lower index) then REDUX max-value /
// min-index (exact jnp.argmax first-occurrence semantics; distances >= 0 so
// float-bit compare == float compare).
// ---------------------------------------------------------------------------
__global__ __launch_bounds__(512, 1) void fps_kernel(const float* __restrict__ xyz)
{
    const int b    = blockIdx.x;
    const int tid  = threadIdx.x;
    const int lane = tid & 31;
    const int w    = tid >> 5;
    const float* bx = xyz + (size_t)b * NN * 3;

    // pair p holds points j=2p (lo) and j=2p+1 (hi); global idx = tid + j*512
    unsigned long long px2[4], py2[4], pz2[4];
    float dist[8];
#pragma unroll
    for (int p = 0; p < 4; ++p) {
        int i0 = tid + (2 * p) * 512;
        int i1 = i0 + 512;
        px2[p] = f2_pack(bx[i0 * 3 + 0], bx[i1 * 3 + 0]);
        py2[p] = f2_pack(bx[i0 * 3 + 1], bx[i1 * 3 + 1]);
        pz2[p] = f2_pack(bx[i0 * 3 + 2], bx[i1 * 3 + 2]);
        dist[2 * p]     = 10000000000.0f;
        dist[2 * p + 1] = 10000000000.0f;
    }

    __shared__ unsigned s_val[16];
    __shared__ unsigned s_idx[16];
    __shared__ int      s_far;

    if (tid == 0) g_fps_idx[b * SS] = 0;

    int far = 0;
    for (int it = 0; it < SS; ++it) {
        const float cx = __ldg(bx + far * 3 + 0);
        const float cy = __ldg(bx + far * 3 + 1);
        const float cz = __ldg(bx + far * 3 + 2);
        const unsigned long long ncx2 = f2_pack(-cx, -cx);
        const unsigned long long ncy2 = f2_pack(-cy, -cy);
        const unsigned long long ncz2 = f2_pack(-cz, -cz);

        float nd[8];
#pragma unroll
        for (int p = 0; p < 4; ++p) {
            unsigned long long dx2 = f2_add(px2[p], ncx2);
            unsigned long long dy2 = f2_add(py2[p], ncy2);
            unsigned long long dz2 = f2_add(pz2[p], ncz2);
            unsigned long long sx  = f2_mul(dx2, dx2);
            unsigned long long sy  = f2_mul(dy2, dy2);
            unsigned long long sz  = f2_mul(dz2, dz2);
            unsigned long long dd2 = f2_add(f2_add(sx, sy), sz);
            float da, db;
            f2_unpack(da, db, dd2);
            nd[2 * p]     = fminf(dist[2 * p],     da);
            nd[2 * p + 1] = fminf(dist[2 * p + 1], db);
            dist[2 * p]     = nd[2 * p];
            dist[2 * p + 1] = nd[2 * p + 1];
        }

        // depth-3 argmax tree; ">= keeps left" == first-occurrence (lower j)
        float v0, v1, v2w, v3, va, vb2, vf;
        int   j0, j1, j2, j3, ja, jb, jf;
        v0 = (nd[0] >= nd[1]) ? nd[0] : nd[1];  j0 = (nd[0] >= nd[1]) ? 0 : 1;
        v1 = (nd[2] >= nd[3]) ? nd[2] : nd[3];  j1 = (nd[2] >= nd[3]) ? 2 : 3;
        v2w = (nd[4] >= nd[5]) ? nd[4] : nd[5]; j2 = (nd[4] >= nd[5]) ? 4 : 5;
        v3 = (nd[6] >= nd[7]) ? nd[6] : nd[7];  j3 = (nd[6] >= nd[7]) ? 6 : 7;
        va = (v0 >= v1) ? v0 : v1;              ja = (v0 >= v1) ? j0 : j1;
        vb2 = (v2w >= v3) ? v2w : v3;           jb = (v2w >= v3) ? j2 : j3;
        vf = (va >= vb2) ? va : vb2;            jf = (va >= vb2) ? ja : jb;

        // warp reduce: max value (as bits, all >= 0), then min index among ties
        unsigned vbits = __float_as_uint(vf);
        unsigned wmax  = __reduce_max_sync(0xffffffffu, vbits);
        unsigned cand  = (vbits == wmax) ? (unsigned)(tid + jf * 512) : 0xffffffffu;
        unsigned wmin  = __reduce_min_sync(0xffffffffu, cand);
        if (lane == 0) { s_val[w] = wmax; s_idx[w] = wmin; }
        __syncthreads();

        if (w == 0) {
            unsigned v16 = (lane < 16) ? s_val[lane] : 0u;
            unsigned i16 = (lane < 16) ? s_idx[lane] : 0xffffffffu;
            unsigned m2  = __reduce_max_sync(0xffffffffu, v16);
            unsigned c2  = (v16 == m2) ? i16 : 0xffffffffu;
            unsigned f2  = __reduce_min_sync(0xffffffffu, c2);
            if (lane == 0) {
                s_far = (int)f2;
                if (it + 1 < SS) g_fps_idx[b * SS + it + 1] = (int)f2;
            }
        }
        __syncthreads();
        far = s_far;
    }
}

// ---------------------------------------------------------------------------
// Fused ball-query + gather (UNCHANGED from the rel_err=0 passing kernel).
// ---------------------------------------------------------------------------
__global__ __launch_bounds__(128) void group_kernel(const float* __restrict__ xyz,
                                                    const float* __restrict__ pts,
                                                    float* __restrict__ out_xyz,
                                                    float* __restrict__ out_pts)
{
    const int bs   = blockIdx.x;        // b*S + s
    const int b    = bs >> 10;
    const int tid  = threadIdx.x;
    const int lane = tid & 31;
    const int w    = tid >> 5;

    const float* bx = xyz + (size_t)b * NN * 3;
    const float* pb = pts + (size_t)b * NN * DD;

    const int a = g_fps_idx[bs];
    const float qx = __ldg(bx + a * 3 + 0);
    const float qy = __ldg(bx + a * 3 + 1);
    const float qz = __ldg(bx + a * 3 + 2);
    const float srcn = __fadd_rn(__fadd_rn(__fmul_rn(qx, qx), __fmul_rn(qy, qy)),
                                 __fmul_rn(qz, qz));
    const float r2 = 0.04f;

    __shared__ int seg_buf[4][KK];
    __shared__ int counts[4];
    __shared__ int gidx[KK];

    // ---- ball query: each warp scans its 1024-point segment in index order
    {
        int cnt = 0;
        const int segbase = w * 1024;
        for (int c = 0; c < 32; ++c) {
            int p = segbase + c * 32 + lane;
            float x = __ldg(bx + p * 3 + 0);
            float y = __ldg(bx + p * 3 + 1);
            float z = __ldg(bx + p * 3 + 2);
            // GEMM-style FMA dot, ascending component order
            float dot = __fmaf_rn(qz, z, __fmaf_rn(qy, y, __fmul_rn(qx, x)));
            float dn  = __fadd_rn(__fadd_rn(__fmul_rn(x, x), __fmul_rn(y, y)),
                                  __fmul_rn(z, z));
            float d   = __fadd_rn(__fadd_rn(__fmul_rn(-2.0f, dot), srcn), dn);
            bool hit = !(d > r2);
            unsigned m = __ballot_sync(0xffffffffu, hit);
            if (hit) {
                int r = cnt + __popc(m & ((1u << lane) - 1u));
                if (r < KK) seg_buf[w][r] = p;
            }
            cnt += __popc(m);
            if (cnt >= KK) break;
        }
        if (lane == 0) counts[w] = cnt < KK ? cnt : KK;
    }
    __syncthreads();

    // ---- merge first-32 across segments (threads 0..31)
    if (tid < KK) {
        int c0 = counts[0], c1 = counts[1], c2 = counts[2], c3 = counts[3];
        int o1 = c0, o2 = c0 + c1, o3 = o2 + c2, tot = o3 + c3;
        int w0 = (c0 > 0) ? 0 : ((c1 > 0) ? 1 : ((c2 > 0) ? 2 : 3));
        int g0 = seg_buf[w0][0];
        int j = tid;
        int g;
        if (j < tot) {
            int ws, off;
            if      (j < o1) { ws = 0; off = j; }
            else if (j < o2) { ws = 1; off = j - o1; }
            else if (j < o3) { ws = 2; off = j - o2; }
            else             { ws = 3; off = j - o3; }
            g = seg_buf[ws][off];
        } else {
            g = g0;  // fill with first in-radius index (anchor guarantees >=1 hit)
        }
        gidx[j] = g;
    }
    // new_xyz
    if (tid < 3) out_xyz[(size_t)bs * 3 + tid] = __ldg(bx + a * 3 + tid);
    __syncthreads();

    // ---- gather + concat writes: row = [points[g] (64) | xyz[g] (3) | points[a] (64)]
    float av  = 0.0f, av2 = 0.0f;
    if (tid >= 67) av  = __ldg(pb + (size_t)a * DD + (tid - 67));
    if (tid < 3)   av2 = __ldg(pb + (size_t)a * DD + 61 + tid);   // elems 128..130 -> anchor[61..63]

    float* base0 = out_pts + (size_t)bs * KK * CDIM;
#pragma unroll 4
    for (int k = 0; k < KK; ++k) {
        int g = gidx[k];
        float v;
        if (tid < 64)      v = __ldg(pb + (size_t)g * DD + tid);
        else if (tid < 67) v = __ldg(bx + (size_t)g * 3 + (tid - 64));
        else               v = av;
        float* row = base0 + (size_t)k * CDIM;
        row[tid] = v;
        if (tid < 3) row[128 + tid] = av2;
    }
}

extern "C" void kernel_launch(void* const* d_in, const int* in_sizes, int n_in,
                              void* d_out, int out_size)
{
    const float* xyz = (const float*)d_in[0];   // [B, N, 3]
    const float* pts = (const float*)d_in[1];   // [B, N, D]
    float* out = (float*)d_out;
    float* out_xyz = out;                       // [B, S, 3]
    float* out_pts = out + (size_t)BB * SS * 3; // [B, S, K, 131]

    fps_kernel<<<BB, 512>>>(xyz);
    group_kernel<<<BB * SS, 128>>>(xyz, pts, out_xyz, out_pts);
}

// round 14
// speedup vs baseline: 1.7539x; 1.1824x over previous
#include <cuda_runtime.h>

#define BB 8
#define NN 4096
#define DD 64
#define SS 1024
#define KK 32
#define CDIM 131   // 64 + 3 + 64

__device__ int g_fps_idx[BB * SS];

// ---- packed f32x2 helpers (per-lane IEEE identical to scalar FADD/FMUL) ----
__device__ __forceinline__ unsigned long long f2_pack(float lo, float hi) {
    unsigned long long r;
    asm("mov.b64 %0, {%1, %2};" : "=l"(r) : "f"(lo), "f"(hi));
    return r;
}
__device__ __forceinline__ void f2_unpack(float& lo, float& hi, unsigned long long v) {
    asm("mov.b64 {%0, %1}, %2;" : "=f"(lo), "=f"(hi) : "l"(v));
}
__device__ __forceinline__ unsigned long long f2_add(unsigned long long a, unsigned long long b) {
    unsigned long long r;
    asm("add.rn.f32x2 %0, %1, %2;" : "=l"(r) : "l"(a), "l"(b));
    return r;
}
__device__ __forceinline__ unsigned long long f2_mul(unsigned long long a, unsigned long long b) {
    unsigned long long r;
    asm("mul.rn.f32x2 %0, %1, %2;" : "=l"(r) : "l"(a), "l"(b));
    return r;
}

// ---------------------------------------------------------------------------
// FPS: one block per batch, 512 threads, 8 points/thread in packed f32x2 regs.
// Arithmetic bit-identical to the verified-exact form:
//   dx = px + (-cx); dd = (dx*dx + dy*dy) + dz*dz; nd = fminf(dist, dd)
// Argmax: depth-3 select tree (>= prefers lower index), REDUX max-value then
// REDUX min-index (exact jnp.argmax first-occurrence; nd >= 0 so uint-bit
// compare == float compare).
// Single barrier per iteration: stage-1 results are double-buffered by it&1,
// and EVERY warp redundantly performs the 16-way stage-2 reduction, so no
// s_far broadcast / second barrier is needed. Centroid coords come from smem.
// ---------------------------------------------------------------------------
__global__ __launch_bounds__(512, 1) void fps_kernel(const float* __restrict__ xyz)
{
    const int b    = blockIdx.x;
    const int tid  = threadIdx.x;
    const int lane = tid & 31;
    const int w    = tid >> 5;
    const float* bx = xyz + (size_t)b * NN * 3;

    __shared__ float sx[NN], sy[NN], sz[NN];      // 48 KB: centroid lookups
    __shared__ unsigned s_val[2][16];
    __shared__ unsigned s_idx[2][16];

    // pair p holds points j=2p (lo) and j=2p+1 (hi); global idx = tid + j*512
    unsigned long long px2[4], py2[4], pz2[4];
    float dist[8];
#pragma unroll
    for (int p = 0; p < 4; ++p) {
        int i0 = tid + (2 * p) * 512;
        int i1 = i0 + 512;
        float x0 = bx[i0 * 3 + 0], y0 = bx[i0 * 3 + 1], z0 = bx[i0 * 3 + 2];
        float x1 = bx[i1 * 3 + 0], y1 = bx[i1 * 3 + 1], z1 = bx[i1 * 3 + 2];
        sx[i0] = x0; sy[i0] = y0; sz[i0] = z0;
        sx[i1] = x1; sy[i1] = y1; sz[i1] = z1;
        px2[p] = f2_pack(x0, x1);
        py2[p] = f2_pack(y0, y1);
        pz2[p] = f2_pack(z0, z1);
        dist[2 * p]     = 10000000000.0f;
        dist[2 * p + 1] = 10000000000.0f;
    }
    __syncthreads();

    int far = 0;
    for (int it = 0; it < SS; ++it) {
        if (tid == 0) g_fps_idx[b * SS + it] = far;

        const float cx = sx[far];
        const float cy = sy[far];
        const float cz = sz[far];
        const unsigned long long ncx2 = f2_pack(-cx, -cx);
        const unsigned long long ncy2 = f2_pack(-cy, -cy);
        const unsigned long long ncz2 = f2_pack(-cz, -cz);

        float nd[8];
#pragma unroll
        for (int p = 0; p < 4; ++p) {
            unsigned long long dx2 = f2_add(px2[p], ncx2);
            unsigned long long dy2 = f2_add(py2[p], ncy2);
            unsigned long long dz2 = f2_add(pz2[p], ncz2);
            unsigned long long sxp = f2_mul(dx2, dx2);
            unsigned long long syp = f2_mul(dy2, dy2);
            unsigned long long szp = f2_mul(dz2, dz2);
            unsigned long long dd2 = f2_add(f2_add(sxp, syp), szp);
            float da, db;
            f2_unpack(da, db, dd2);
            nd[2 * p]     = fminf(dist[2 * p],     da);
            nd[2 * p + 1] = fminf(dist[2 * p + 1], db);
            dist[2 * p]     = nd[2 * p];
            dist[2 * p + 1] = nd[2 * p + 1];
        }

        // depth-3 argmax tree; ">= keeps left" == first-occurrence (lower j)
        float v0, v1, v2w, v3, va, vb2, vf;
        int   j0, j1, j2, j3, ja, jb, jf;
        v0 = (nd[0] >= nd[1]) ? nd[0] : nd[1];  j0 = (nd[0] >= nd[1]) ? 0 : 1;
        v1 = (nd[2] >= nd[3]) ? nd[2] : nd[3];  j1 = (nd[2] >= nd[3]) ? 2 : 3;
        v2w = (nd[4] >= nd[5]) ? nd[4] : nd[5]; j2 = (nd[4] >= nd[5]) ? 4 : 5;
        v3 = (nd[6] >= nd[7]) ? nd[6] : nd[7];  j3 = (nd[6] >= nd[7]) ? 6 : 7;
        va = (v0 >= v1) ? v0 : v1;              ja = (v0 >= v1) ? j0 : j1;
        vb2 = (v2w >= v3) ? v2w : v3;           jb = (v2w >= v3) ? j2 : j3;
        vf = (va >= vb2) ? va : vb2;            jf = (va >= vb2) ? ja : jb;

        // warp reduce: max value (as bits, all >= 0), then min index among ties
        const int pbuf = it & 1;
        unsigned vbits = __float_as_uint(vf);
        unsigned wmax  = __reduce_max_sync(0xffffffffu, vbits);
        unsigned cand  = (vbits == wmax) ? (unsigned)(tid + jf * 512) : 0xffffffffu;
        unsigned wmin  = __reduce_min_sync(0xffffffffu, cand);
        if (lane == 0) { s_val[pbuf][w] = wmax; s_idx[pbuf][w] = wmin; }
        __syncthreads();

        // stage 2: every warp reduces the 16 per-warp results redundantly
        unsigned v16 = (lane < 16) ? s_val[pbuf][lane] : 0u;
        unsigned i16 = (lane < 16) ? s_idx[pbuf][lane] : 0xffffffffu;
        unsigned m2  = __reduce_max_sync(0xffffffffu, v16);
        unsigned c2  = (v16 == m2) ? i16 : 0xffffffffu;
        far = (int)__reduce_min_sync(0xffffffffu, c2);
    }
}

// ---------------------------------------------------------------------------
// Fused ball-query + gather (UNCHANGED from the rel_err=0 passing kernel).
// ---------------------------------------------------------------------------
__global__ __launch_bounds__(128) void group_kernel(const float* __restrict__ xyz,
                                                    const float* __restrict__ pts,
                                                    float* __restrict__ out_xyz,
                                                    float* __restrict__ out_pts)
{
    const int bs   = blockIdx.x;        // b*S + s
    const int b    = bs >> 10;
    const int tid  = threadIdx.x;
    const int lane = tid & 31;
    const int w    = tid >> 5;

    const float* bx = xyz + (size_t)b * NN * 3;
    const float* pb = pts + (size_t)b * NN * DD;

    const int a = g_fps_idx[bs];
    const float qx = __ldg(bx + a * 3 + 0);
    const float qy = __ldg(bx + a * 3 + 1);
    const float qz = __ldg(bx + a * 3 + 2);
    const float srcn = __fadd_rn(__fadd_rn(__fmul_rn(qx, qx), __fmul_rn(qy, qy)),
                                 __fmul_rn(qz, qz));
    const float r2 = 0.04f;

    __shared__ int seg_buf[4][KK];
    __shared__ int counts[4];
    __shared__ int gidx[KK];

    // ---- ball query: each warp scans its 1024-point segment in index order
    {
        int cnt = 0;
        const int segbase = w * 1024;
        for (int c = 0; c < 32; ++c) {
            int p = segbase + c * 32 + lane;
            float x = __ldg(bx + p * 3 + 0);
            float y = __ldg(bx + p * 3 + 1);
            float z = __ldg(bx + p * 3 + 2);
            // GEMM-style FMA dot, ascending component order
            float dot = __fmaf_rn(qz, z, __fmaf_rn(qy, y, __fmul_rn(qx, x)));
            float dn  = __fadd_rn(__fadd_rn(__fmul_rn(x, x), __fmul_rn(y, y)),
                                  __fmul_rn(z, z));
            float d   = __fadd_rn(__fadd_rn(__fmul_rn(-2.0f, dot), srcn), dn);
            bool hit = !(d > r2);
            unsigned m = __ballot_sync(0xffffffffu, hit);
            if (hit) {
                int r = cnt + __popc(m & ((1u << lane) - 1u));
                if (r < KK) seg_buf[w][r] = p;
            }
            cnt += __popc(m);
            if (cnt >= KK) break;
        }
        if (lane == 0) counts[w] = cnt < KK ? cnt : KK;
    }
    __syncthreads();

    // ---- merge first-32 across segments (threads 0..31)
    if (tid < KK) {
        int c0 = counts[0], c1 = counts[1], c2 = counts[2], c3 = counts[3];
        int o1 = c0, o2 = c0 + c1, o3 = o2 + c2, tot = o3 + c3;
        int w0 = (c0 > 0) ? 0 : ((c1 > 0) ? 1 : ((c2 > 0) ? 2 : 3));
        int g0 = seg_buf[w0][0];
        int j = tid;
        int g;
        if (j < tot) {
            int ws, off;
            if      (j < o1) { ws = 0; off = j; }
            else if (j < o2) { ws = 1; off = j - o1; }
            else if (j < o3) { ws = 2; off = j - o2; }
            else             { ws = 3; off = j - o3; }
            g = seg_buf[ws][off];
        } else {
            g = g0;  // fill with first in-radius index (anchor guarantees >=1 hit)
        }
        gidx[j] = g;
    }
    // new_xyz
    if (tid < 3) out_xyz[(size_t)bs * 3 + tid] = __ldg(bx + a * 3 + tid);
    __syncthreads();

    // ---- gather + concat writes: row = [points[g] (64) | xyz[g] (3) | points[a] (64)]
    float av  = 0.0f, av2 = 0.0f;
    if (tid >= 67) av  = __ldg(pb + (size_t)a * DD + (tid - 67));
    if (tid < 3)   av2 = __ldg(pb + (size_t)a * DD + 61 + tid);   // elems 128..130 -> anchor[61..63]

    float* base0 = out_pts + (size_t)bs * KK * CDIM;
#pragma unroll 4
    for (int k = 0; k < KK; ++k) {
        int g = gidx[k];
        float v;
        if (tid < 64)      v = __ldg(pb + (size_t)g * DD + tid);
        else if (tid < 67) v = __ldg(bx + (size_t)g * 3 + (tid - 64));
        else               v = av;
        float* row = base0 + (size_t)k * CDIM;
        row[tid] = v;
        if (tid < 3) row[128 + tid] = av2;
    }
}

extern "C" void kernel_launch(void* const* d_in, const int* in_sizes, int n_in,
                              void* d_out, int out_size)
{
    const float* xyz = (const float*)d_in[0];   // [B, N, 3]
    const float* pts = (const float*)d_in[1];   // [B, N, D]
    float* out = (float*)d_out;
    float* out_xyz = out;                       // [B, S, 3]
    float* out_pts = out + (size_t)BB * SS * 3; // [B, S, K, 131]

    fps_kernel<<<BB, 512>>>(xyz);
    group_kernel<<<BB * SS, 128>>>(xyz, pts, out_xyz, out_pts);
}